// round 8
// baseline (speedup 1.0000x reference)
#include <cuda_runtime.h>
#include <math.h>
#include <stdint.h>

#define NV 6890
#define NF 13776
#define NB 2

// winding: split triangle dim SW ways; 2 points per thread; triangles in pairs
#define SW 12
#define WCHUNK 1148            // NF/SW exact, even
#define WTILE 128
#define PHALF 3456             // 54 blocks * 64 threads

// pairwise: split i dim SP ways, 2 j's per thread
#define SP 24
#define PCHUNK 288
#define TI 128

__device__ float4 d_triA[NB * NF];
__device__ float4 d_triB[NB * NF];
__device__ float4 d_triC[NB * NF];
__device__ float4 d_triN[NB * NF];     // (nx, ny, nz, d0)
__device__ float  d_wnp[SW][NB * NV];
__device__ float  d_pmin[SP][NB * NV];

__device__ __forceinline__ float rcp_fast(float x) {
    float r; asm("rcp.approx.f32 %0, %1;" : "=f"(r) : "f"(x)); return r;
}
__device__ __forceinline__ float sqrt_fast(float x) {
    float r; asm("sqrt.approx.f32 %0, %1;" : "=f"(r) : "f"(x)); return r;
}

__device__ __forceinline__ float fast_atan2f(float y, float x) {
    float ax = fabsf(x), ay = fabsf(y);
    float mx = fmaxf(ax, ay), mn = fminf(ax, ay);
    float t = mn * rcp_fast(fmaxf(mx, 1e-37f));   // mx==0 -> t = 0
    float s = t * t;
    float u;
    u = 0.00282363896258175373077393f;
    u = fmaf(u, s, -0.0159569028764963150024414f);
    u = fmaf(u, s,  0.0425049886107444763183594f);
    u = fmaf(u, s, -0.0748900920152664184570312f);
    u = fmaf(u, s,  0.106347933411598205566406f);
    u = fmaf(u, s, -0.142027363181114196777344f);
    u = fmaf(u, s,  0.199926957488059997558594f);
    u = fmaf(u, s, -0.333331018686294555664062f);
    float r = fmaf(u * s, t, t);                  // atan(mn/mx) in [0, pi/4]
    r = (ay > ax) ? 1.57079632679489662f - r : r;
    r = (x < 0.0f) ? 3.14159265358979323f - r : r;
    return copysignf(r, y);
}

// geometry for one point-triangle: returns w = (denom, det), with the
// degenerate p==vertex case substituted by (1, 0)  (theta = 0).
__device__ __forceinline__ void wn_w(
    float npx, float npy, float npz,
    const float4& A, const float4& B, const float4& C, const float4& N,
    float& wx, float& wy)
{
    float ax = A.x + npx, ay = A.y + npy, az = A.z + npz;
    float bx = B.x + npx, by = B.y + npy, bz = B.z + npz;
    float cx = C.x + npx, cy = C.y + npy, cz = C.z + npz;

    float na2 = fmaf(ax, ax, fmaf(ay, ay, az * az));
    float nb2 = fmaf(bx, bx, fmaf(by, by, bz * bz));
    float nc2 = fmaf(cx, cx, fmaf(cy, cy, cz * cz));
    float na = sqrt_fast(na2);
    float nb = sqrt_fast(nb2);
    float nc = sqrt_fast(nc2);

    float ab  = fmaf(az, bz, fmaf(ay, by, ax * bx));
    float bc  = fmaf(bz, cz, fmaf(by, cy, bx * cx));
    float ca  = fmaf(cz, az, fmaf(cy, ay, cx * ax));

    float det = fmaf(npz, N.z, fmaf(npy, N.y, fmaf(npx, N.x, N.w)));
    float den = fmaf(ca, nb, fmaf(bc, na, fmaf(ab, nc, (na * nb) * nc)));

    float m = fminf(fminf(na2, nb2), nc2);
    wx = (m == 0.0f) ? 1.0f : den;
    wy = (m == 0.0f) ? 0.0f : det;
}

// theta1 + theta2 from two (denom, det) pairs via complex product + wrap fix
__device__ __forceinline__ float pair_angle(float x1, float y1, float x2, float y2) {
    float zr = fmaf(x1, x2, -(y1 * y2));
    float zi = fmaf(x1, y2, y1 * x2);
    float ph = fast_atan2f(zi, zr);
    int n1 = __float_as_int(y1) >> 31;    // -1 if theta1 < 0 (incl -0)
    int n2 = __float_as_int(y2) >> 31;
    bool bothpos = (n1 | n2) == 0;
    bool bothneg = (n1 & n2) != 0;
    float c = (bothpos && ph < 0.0f) ?  6.28318530717958648f :
              ((bothneg && ph > 0.0f) ? -6.28318530717958648f : 0.0f);
    return ph + c;
}

__global__ void gather_tris(const float* __restrict__ verts,
                            const int* __restrict__ faces) {
    int idx = blockIdx.x * blockDim.x + threadIdx.x;
    if (idx >= NB * NF) return;
    int b = idx / NF, t = idx - b * NF;
    int i0 = faces[3 * t + 0];
    int i1 = faces[3 * t + 1];
    int i2 = faces[3 * t + 2];
    const float* vb = verts + (size_t)b * NV * 3;
    float Axv = vb[3*i0], Ayv = vb[3*i0+1], Azv = vb[3*i0+2];
    float Bxv = vb[3*i1], Byv = vb[3*i1+1], Bzv = vb[3*i1+2];
    float Cxv = vb[3*i2], Cyv = vb[3*i2+1], Czv = vb[3*i2+2];
    d_triA[idx] = make_float4(Axv, Ayv, Azv, 0.f);
    d_triB[idx] = make_float4(Bxv, Byv, Bzv, 0.f);
    d_triC[idx] = make_float4(Cxv, Cyv, Czv, 0.f);

    float bcx = fmaf(Byv, Czv, -(Bzv * Cyv));
    float bcy = fmaf(Bzv, Cxv, -(Bxv * Czv));
    float bcz = fmaf(Bxv, Cyv, -(Byv * Cxv));
    float abx = fmaf(Ayv, Bzv, -(Azv * Byv));
    float aby = fmaf(Azv, Bxv, -(Axv * Bzv));
    float abz = fmaf(Axv, Byv, -(Ayv * Bxv));
    float cax = fmaf(Cyv, Azv, -(Czv * Ayv));
    float cay = fmaf(Czv, Axv, -(Cxv * Azv));
    float caz = fmaf(Cxv, Ayv, -(Cyv * Axv));

    float nx = abx + bcx + cax;
    float ny = aby + bcy + cay;
    float nz = abz + bcz + caz;
    float d0 = fmaf(Azv, bcz, fmaf(Ayv, bcy, Axv * bcx));   // A.(BxC)
    d_triN[idx] = make_float4(nx, ny, nz, d0);
}

__global__ void __launch_bounds__(64) winding_kernel(const float* __restrict__ verts) {
    __shared__ float4 sA[WTILE], sB[WTILE], sC[WTILE], sN[WTILE];
    const int b = blockIdx.z;
    const int s = blockIdx.y;
    const int p0 = blockIdx.x * 64 + threadIdx.x;   // < PHALF
    const int p1r = p0 + PHALF;
    const int p1 = min(p1r, NV - 1);

    const float* vp0 = verts + ((size_t)b * NV + p0) * 3;
    const float npx0 = -vp0[0], npy0 = -vp0[1], npz0 = -vp0[2];
    const float* vp1 = verts + ((size_t)b * NV + p1) * 3;
    const float npx1 = -vp1[0], npy1 = -vp1[1], npz1 = -vp1[2];

    const int t0 = s * WCHUNK;
    const int t1 = t0 + WCHUNK;
    float acc0 = 0.f, acc1 = 0.f;

    for (int base = t0; base < t1; base += WTILE) {
        int cnt = min(WTILE, t1 - base);        // always even (128 or 124)
        __syncthreads();
        for (int k = threadIdx.x; k < cnt; k += 64) {
            sA[k] = d_triA[b * NF + base + k];
            sB[k] = d_triB[b * NF + base + k];
            sC[k] = d_triC[b * NF + base + k];
            sN[k] = d_triN[b * NF + base + k];
        }
        __syncthreads();
        #pragma unroll 2
        for (int k = 0; k < cnt; k += 2) {
            float4 A0 = sA[k],   B0 = sB[k],   C0 = sC[k],   N0 = sN[k];
            float4 A1 = sA[k+1], B1 = sB[k+1], C1 = sC[k+1], N1 = sN[k+1];
            float x1, y1, x2, y2;
            wn_w(npx0, npy0, npz0, A0, B0, C0, N0, x1, y1);
            wn_w(npx0, npy0, npz0, A1, B1, C1, N1, x2, y2);
            acc0 += pair_angle(x1, y1, x2, y2);
            wn_w(npx1, npy1, npz1, A0, B0, C0, N0, x1, y1);
            wn_w(npx1, npy1, npz1, A1, B1, C1, N1, x2, y2);
            acc1 += pair_angle(x1, y1, x2, y2);
        }
    }
    d_wnp[s][b * NV + p0] = acc0;
    if (p1r < NV) d_wnp[s][b * NV + p1r] = acc1;
}

__global__ void pairwise_kernel(const float* __restrict__ verts,
                                const int* __restrict__ gm) {
    __shared__ float sx0[TI], sy0[TI], sz0[TI], sq0[TI];
    __shared__ float sx1[TI], sy1[TI], sz1[TI], sq1[TI];

    const int s  = blockIdx.y;
    const int j0 = (blockIdx.x * blockDim.x + threadIdx.x) * 2;
    const bool jv = j0 < NV;

    float xa0=0,ya0=0,za0=0,qa0=0, xa1=0,ya1=0,za1=0,qa1=0;
    float xb0=0,yb0=0,zb0=0,qb0=0, xb1=0,yb1=0,zb1=0,qb1=0;
    if (jv) {
        const float* v = verts + (size_t)j0 * 3;
        xa0 = v[0]; ya0 = v[1]; za0 = v[2];
        xa1 = v[3]; ya1 = v[4]; za1 = v[5];
        qa0 = (xa0*xa0 + ya0*ya0) + za0*za0;
        qa1 = (xa1*xa1 + ya1*ya1) + za1*za1;
        const float* w = verts + ((size_t)NV + j0) * 3;
        xb0 = w[0]; yb0 = w[1]; zb0 = w[2];
        xb1 = w[3]; yb1 = w[4]; zb1 = w[5];
        qb0 = (xb0*xb0 + yb0*yb0) + zb0*zb0;
        qb1 = (xb1*xb1 + yb1*yb1) + zb1*zb1;
    }

    const float INF = __int_as_float(0x7f800000);
    float m00 = INF, m01 = INF, m10 = INF, m11 = INF;

    const int i0 = s * PCHUNK;
    const int i1 = min(NV, i0 + PCHUNK);

    for (int base = i0; base < i1; base += TI) {
        int cnt = min(TI, i1 - base);
        __syncthreads();
        for (int k = threadIdx.x; k < cnt; k += blockDim.x) {
            int i = base + k;
            const float* v = verts + (size_t)i * 3;
            float x = v[0], y = v[1], z = v[2];
            sx0[k] = x; sy0[k] = y; sz0[k] = z;
            sq0[k] = (x*x + y*y) + z*z;
            const float* w = verts + ((size_t)NV + i) * 3;
            x = w[0]; y = w[1]; z = w[2];
            sx1[k] = x; sy1[k] = y; sz1[k] = z;
            sq1[k] = (x*x + y*y) + z*z;
        }
        __syncthreads();
        if (jv) {
            const int* mp = gm + (size_t)base * NV + j0;
            for (int k = 0; k < cnt; k++) {
                int2 mm = *(const int2*)mp;
                mp += NV;
                float xi = sx0[k], yi = sy0[k], zi = sz0[k], qi = sq0[k];
                float dot0 = fmaf(zi, za0, fmaf(yi, ya0, xi * xa0));
                float d2_0 = fmaf(-2.f, dot0, qi + qa0);
                float dot1 = fmaf(zi, za1, fmaf(yi, ya1, xi * xa1));
                float d2_1 = fmaf(-2.f, dot1, qi + qa1);
                if (mm.x) m00 = fminf(m00, d2_0);
                if (mm.y) m01 = fminf(m01, d2_1);
                xi = sx1[k]; yi = sy1[k]; zi = sz1[k]; qi = sq1[k];
                float e0 = fmaf(zi, zb0, fmaf(yi, yb0, xi * xb0));
                float f0 = fmaf(-2.f, e0, qi + qb0);
                float e1 = fmaf(zi, zb1, fmaf(yi, yb1, xi * xb1));
                float f1 = fmaf(-2.f, e1, qi + qb1);
                if (mm.x) m10 = fminf(m10, f0);
                if (mm.y) m11 = fminf(m11, f1);
            }
        }
    }
    if (jv) {
        d_pmin[s][j0]          = m00;
        d_pmin[s][j0 + 1]      = m01;
        d_pmin[s][NV + j0]     = m10;
        d_pmin[s][NV + j0 + 1] = m11;
    }
}

__global__ void finalize_kernel(float* __restrict__ out) {
    int idx = blockIdx.x * blockDim.x + threadIdx.x;
    if (idx >= NB * NV) return;
    const float INF = __int_as_float(0x7f800000);
    float mn = INF;
    #pragma unroll
    for (int s = 0; s < SP; s++) mn = fminf(mn, d_pmin[s][idx]);
    float v = sqrtf(fmaxf(mn, 1e-12f));

    float acc = 0.f;
    #pragma unroll
    for (int s = 0; s < SW; s++) acc += d_wnp[s][idx];
    float wn = (2.0f * acc) / 12.566370614359172f;

    out[idx]               = v;
    out[NB * NV + idx]     = (v < 0.02f) ? 1.0f : 0.0f;
    out[2 * NB * NV + idx] = (wn <= 0.99f) ? 1.0f : 0.0f;
}

extern "C" void kernel_launch(void* const* d_in, const int* in_sizes, int n_in,
                              void* d_out, int out_size) {
    const float* verts = (const float*)d_in[0];
    const int*   faces = (const int*)d_in[1];
    const int*   gm    = (const int*)d_in[2];
    float* out = (float*)d_out;

    gather_tris<<<(NB * NF + 255) / 256, 256>>>(verts, faces);

    dim3 gw(54, SW, NB);                 // 54 x 12 x 2 = 1296 blocks, 64 thr
    winding_kernel<<<gw, 64>>>(verts);

    dim3 gp((NV + 511) / 512, SP);       // 336 blocks
    pairwise_kernel<<<gp, 256>>>(verts, gm);

    finalize_kernel<<<(NB * NV + 255) / 256, 256>>>(out);
}

// round 9
// speedup vs baseline: 1.0245x; 1.0245x over previous
#include <cuda_runtime.h>
#include <math.h>
#include <stdint.h>

#define NV 6890
#define NF 13776
#define NB 2

// winding: split triangle dim SW ways; 2 points per thread; triangles in pairs
#define SW 12
#define WCHUNK 1148            // NF/SW exact, even
#define WTILE 128
#define PHALF 3456             // 54 blocks * 64 threads

// pairwise: split i dim SP ways, 2 j's per thread
#define SP 24
#define PCHUNK 288
#define TI 128

__device__ float4 d_triA[NB * NF];
__device__ float4 d_triB[NB * NF];
__device__ float4 d_triC[NB * NF];
__device__ float4 d_triN[NB * NF];     // (nx, ny, nz, d0)
__device__ float  d_wnp[SW][NB * NV];
__device__ float  d_pmin[SP][NB * NV];

__device__ __forceinline__ float rcp_fast(float x) {
    float r; asm("rcp.approx.f32 %0, %1;" : "=f"(r) : "f"(x)); return r;
}
__device__ __forceinline__ float sqrt_fast(float x) {
    float r; asm("sqrt.approx.f32 %0, %1;" : "=f"(r) : "f"(x)); return r;
}

__device__ __forceinline__ float fast_atan2f(float y, float x) {
    float ax = fabsf(x), ay = fabsf(y);
    float mx = fmaxf(ax, ay), mn = fminf(ax, ay);
    float t = mn * rcp_fast(fmaxf(mx, 1e-37f));   // mx==0 -> t = 0
    float s = t * t;
    float u;
    u = 0.00282363896258175373077393f;
    u = fmaf(u, s, -0.0159569028764963150024414f);
    u = fmaf(u, s,  0.0425049886107444763183594f);
    u = fmaf(u, s, -0.0748900920152664184570312f);
    u = fmaf(u, s,  0.106347933411598205566406f);
    u = fmaf(u, s, -0.142027363181114196777344f);
    u = fmaf(u, s,  0.199926957488059997558594f);
    u = fmaf(u, s, -0.333331018686294555664062f);
    float r = fmaf(u * s, t, t);                  // atan(mn/mx) in [0, pi/4]
    r = (ay > ax) ? 1.57079632679489662f - r : r;
    r = (x < 0.0f) ? 3.14159265358979323f - r : r;
    return copysignf(r, y);
}

// geometry for one point-triangle: returns w = (denom, det), with the
// degenerate p==vertex case substituted by (1, +0)  (theta = 0).
__device__ __forceinline__ void wn_w(
    float npx, float npy, float npz,
    const float4& A, const float4& B, const float4& C, const float4& N,
    float& wx, float& wy)
{
    float ax = A.x + npx, ay = A.y + npy, az = A.z + npz;
    float bx = B.x + npx, by = B.y + npy, bz = B.z + npz;
    float cx = C.x + npx, cy = C.y + npy, cz = C.z + npz;

    float na2 = fmaf(ax, ax, fmaf(ay, ay, az * az));
    float nb2 = fmaf(bx, bx, fmaf(by, by, bz * bz));
    float nc2 = fmaf(cx, cx, fmaf(cy, cy, cz * cz));
    float na = sqrt_fast(na2);
    float nb = sqrt_fast(nb2);
    float nc = sqrt_fast(nc2);

    float ab  = fmaf(az, bz, fmaf(ay, by, ax * bx));
    float bc  = fmaf(bz, cz, fmaf(by, cy, bx * cx));
    float ca  = fmaf(cz, az, fmaf(cy, ay, cx * ax));

    float det = fmaf(npz, N.z, fmaf(npy, N.y, fmaf(npx, N.x, N.w)));

    // den = nc*(na*nb + ab) + (na*bc + nb*ca)   (1 mul + 3 fma)
    float t1  = fmaf(na, nb, ab);
    float v   = fmaf(na, bc, nb * ca);
    float den = fmaf(nc, t1, v);

    float m = fminf(fminf(na2, nb2), nc2);
    wx = (m == 0.0f) ? 1.0f : den;
    wy = (m == 0.0f) ? 0.0f : det;
}

// theta1 + theta2 via complex product; 2*pi wrap recovered branch-free
// from the sign bits of y1, y2, ph (ALU-pipe logic only + 1 FADD).
__device__ __forceinline__ float pair_angle(float x1, float y1, float x2, float y2) {
    float zr = fmaf(x1, x2, -(y1 * y2));
    float zi = fmaf(x1, y2, y1 * x2);
    float ph = fast_atan2f(zi, zr);
    int s1 = __float_as_int(y1) >> 31;        // -1 iff sign bit set
    int s2 = __float_as_int(y2) >> 31;
    int sp = __float_as_int(ph) >> 31;
    int addm = ~s1 & ~s2 & sp;                // both thetas >=0, ph<0  -> +2pi
    int subm = s1 & s2 & ~sp;                 // both thetas <0, ph>=0 -> -2pi
    float c = __int_as_float((addm & 0x40C90FDB) | (subm & 0xC0C90FDB));
    return ph + c;
}

__global__ void gather_tris(const float* __restrict__ verts,
                            const int* __restrict__ faces) {
    int idx = blockIdx.x * blockDim.x + threadIdx.x;
    if (idx >= NB * NF) return;
    int b = idx / NF, t = idx - b * NF;
    int i0 = faces[3 * t + 0];
    int i1 = faces[3 * t + 1];
    int i2 = faces[3 * t + 2];
    const float* vb = verts + (size_t)b * NV * 3;
    float Axv = vb[3*i0], Ayv = vb[3*i0+1], Azv = vb[3*i0+2];
    float Bxv = vb[3*i1], Byv = vb[3*i1+1], Bzv = vb[3*i1+2];
    float Cxv = vb[3*i2], Cyv = vb[3*i2+1], Czv = vb[3*i2+2];
    d_triA[idx] = make_float4(Axv, Ayv, Azv, 0.f);
    d_triB[idx] = make_float4(Bxv, Byv, Bzv, 0.f);
    d_triC[idx] = make_float4(Cxv, Cyv, Czv, 0.f);

    float bcx = fmaf(Byv, Czv, -(Bzv * Cyv));
    float bcy = fmaf(Bzv, Cxv, -(Bxv * Czv));
    float bcz = fmaf(Bxv, Cyv, -(Byv * Cxv));
    float abx = fmaf(Ayv, Bzv, -(Azv * Byv));
    float aby = fmaf(Azv, Bxv, -(Axv * Bzv));
    float abz = fmaf(Axv, Byv, -(Ayv * Bxv));
    float cax = fmaf(Cyv, Azv, -(Czv * Ayv));
    float cay = fmaf(Czv, Axv, -(Cxv * Azv));
    float caz = fmaf(Cxv, Ayv, -(Cyv * Axv));

    float nx = abx + bcx + cax;
    float ny = aby + bcy + cay;
    float nz = abz + bcz + caz;
    float d0 = fmaf(Azv, bcz, fmaf(Ayv, bcy, Axv * bcx));   // A.(BxC)
    d_triN[idx] = make_float4(nx, ny, nz, d0);
}

__global__ void __launch_bounds__(64) winding_kernel(const float* __restrict__ verts) {
    __shared__ float4 sA[WTILE], sB[WTILE], sC[WTILE], sN[WTILE];
    const int b = blockIdx.z;
    const int s = blockIdx.y;
    const int p0 = blockIdx.x * 64 + threadIdx.x;   // < PHALF
    const int p1r = p0 + PHALF;
    const int p1 = min(p1r, NV - 1);

    const float* vp0 = verts + ((size_t)b * NV + p0) * 3;
    const float npx0 = -vp0[0], npy0 = -vp0[1], npz0 = -vp0[2];
    const float* vp1 = verts + ((size_t)b * NV + p1) * 3;
    const float npx1 = -vp1[0], npy1 = -vp1[1], npz1 = -vp1[2];

    const int t0 = s * WCHUNK;
    const int t1 = t0 + WCHUNK;
    float acc0 = 0.f, acc1 = 0.f;

    for (int base = t0; base < t1; base += WTILE) {
        int cnt = min(WTILE, t1 - base);        // always even (128 or 124)
        __syncthreads();
        for (int k = threadIdx.x; k < cnt; k += 64) {
            sA[k] = d_triA[b * NF + base + k];
            sB[k] = d_triB[b * NF + base + k];
            sC[k] = d_triC[b * NF + base + k];
            sN[k] = d_triN[b * NF + base + k];
        }
        __syncthreads();
        for (int k = 0; k < cnt; k += 2) {
            float x1, y1, x2, y2;
            wn_w(npx0, npy0, npz0, sA[k],   sB[k],   sC[k],   sN[k],   x1, y1);
            wn_w(npx0, npy0, npz0, sA[k+1], sB[k+1], sC[k+1], sN[k+1], x2, y2);
            acc0 += pair_angle(x1, y1, x2, y2);
            wn_w(npx1, npy1, npz1, sA[k],   sB[k],   sC[k],   sN[k],   x1, y1);
            wn_w(npx1, npy1, npz1, sA[k+1], sB[k+1], sC[k+1], sN[k+1], x2, y2);
            acc1 += pair_angle(x1, y1, x2, y2);
        }
    }
    d_wnp[s][b * NV + p0] = acc0;
    if (p1r < NV) d_wnp[s][b * NV + p1r] = acc1;
}

__global__ void pairwise_kernel(const float* __restrict__ verts,
                                const int* __restrict__ gm) {
    __shared__ float sx0[TI], sy0[TI], sz0[TI], sq0[TI];
    __shared__ float sx1[TI], sy1[TI], sz1[TI], sq1[TI];

    const int s  = blockIdx.y;
    const int j0 = (blockIdx.x * blockDim.x + threadIdx.x) * 2;
    const bool jv = j0 < NV;

    float xa0=0,ya0=0,za0=0,qa0=0, xa1=0,ya1=0,za1=0,qa1=0;
    float xb0=0,yb0=0,zb0=0,qb0=0, xb1=0,yb1=0,zb1=0,qb1=0;
    if (jv) {
        const float* v = verts + (size_t)j0 * 3;
        xa0 = v[0]; ya0 = v[1]; za0 = v[2];
        xa1 = v[3]; ya1 = v[4]; za1 = v[5];
        qa0 = (xa0*xa0 + ya0*ya0) + za0*za0;
        qa1 = (xa1*xa1 + ya1*ya1) + za1*za1;
        const float* w = verts + ((size_t)NV + j0) * 3;
        xb0 = w[0]; yb0 = w[1]; zb0 = w[2];
        xb1 = w[3]; yb1 = w[4]; zb1 = w[5];
        qb0 = (xb0*xb0 + yb0*yb0) + zb0*zb0;
        qb1 = (xb1*xb1 + yb1*yb1) + zb1*zb1;
    }

    const float INF = __int_as_float(0x7f800000);
    float m00 = INF, m01 = INF, m10 = INF, m11 = INF;

    const int i0 = s * PCHUNK;
    const int i1 = min(NV, i0 + PCHUNK);

    for (int base = i0; base < i1; base += TI) {
        int cnt = min(TI, i1 - base);
        __syncthreads();
        for (int k = threadIdx.x; k < cnt; k += blockDim.x) {
            int i = base + k;
            const float* v = verts + (size_t)i * 3;
            float x = v[0], y = v[1], z = v[2];
            sx0[k] = x; sy0[k] = y; sz0[k] = z;
            sq0[k] = (x*x + y*y) + z*z;
            const float* w = verts + ((size_t)NV + i) * 3;
            x = w[0]; y = w[1]; z = w[2];
            sx1[k] = x; sy1[k] = y; sz1[k] = z;
            sq1[k] = (x*x + y*y) + z*z;
        }
        __syncthreads();
        if (jv) {
            const int* mp = gm + (size_t)base * NV + j0;
            for (int k = 0; k < cnt; k++) {
                int2 mm = *(const int2*)mp;
                mp += NV;
                float xi = sx0[k], yi = sy0[k], zi = sz0[k], qi = sq0[k];
                float dot0 = fmaf(zi, za0, fmaf(yi, ya0, xi * xa0));
                float d2_0 = fmaf(-2.f, dot0, qi + qa0);
                float dot1 = fmaf(zi, za1, fmaf(yi, ya1, xi * xa1));
                float d2_1 = fmaf(-2.f, dot1, qi + qa1);
                if (mm.x) m00 = fminf(m00, d2_0);
                if (mm.y) m01 = fminf(m01, d2_1);
                xi = sx1[k]; yi = sy1[k]; zi = sz1[k]; qi = sq1[k];
                float e0 = fmaf(zi, zb0, fmaf(yi, yb0, xi * xb0));
                float f0 = fmaf(-2.f, e0, qi + qb0);
                float e1 = fmaf(zi, zb1, fmaf(yi, yb1, xi * xb1));
                float f1 = fmaf(-2.f, e1, qi + qb1);
                if (mm.x) m10 = fminf(m10, f0);
                if (mm.y) m11 = fminf(m11, f1);
            }
        }
    }
    if (jv) {
        d_pmin[s][j0]          = m00;
        d_pmin[s][j0 + 1]      = m01;
        d_pmin[s][NV + j0]     = m10;
        d_pmin[s][NV + j0 + 1] = m11;
    }
}

__global__ void finalize_kernel(float* __restrict__ out) {
    int idx = blockIdx.x * blockDim.x + threadIdx.x;
    if (idx >= NB * NV) return;
    const float INF = __int_as_float(0x7f800000);
    float mn = INF;
    #pragma unroll
    for (int s = 0; s < SP; s++) mn = fminf(mn, d_pmin[s][idx]);
    float v = sqrtf(fmaxf(mn, 1e-12f));

    float acc = 0.f;
    #pragma unroll
    for (int s = 0; s < SW; s++) acc += d_wnp[s][idx];
    float wn = (2.0f * acc) / 12.566370614359172f;

    out[idx]               = v;
    out[NB * NV + idx]     = (v < 0.02f) ? 1.0f : 0.0f;
    out[2 * NB * NV + idx] = (wn <= 0.99f) ? 1.0f : 0.0f;
}

extern "C" void kernel_launch(void* const* d_in, const int* in_sizes, int n_in,
                              void* d_out, int out_size) {
    const float* verts = (const float*)d_in[0];
    const int*   faces = (const int*)d_in[1];
    const int*   gm    = (const int*)d_in[2];
    float* out = (float*)d_out;

    gather_tris<<<(NB * NF + 255) / 256, 256>>>(verts, faces);

    dim3 gw(54, SW, NB);                 // 54 x 12 x 2 = 1296 blocks, 64 thr
    winding_kernel<<<gw, 64>>>(verts);

    dim3 gp((NV + 511) / 512, SP);       // 336 blocks
    pairwise_kernel<<<gp, 256>>>(verts, gm);

    finalize_kernel<<<(NB * NV + 255) / 256, 256>>>(out);
}

// round 10
// speedup vs baseline: 1.0977x; 1.0715x over previous
#include <cuda_runtime.h>
#include <math.h>
#include <stdint.h>

#define NV 6890
#define NF 13776
#define NB 2

// winding: split triangle dim SW ways; 2 points per thread
#define SW 16
#define WCHUNK 861             // NF/SW exact
#define WTILE 128
#define PHALF 3456             // 54 blocks * 64 threads

// pairwise: split i dim SP ways, 2 j's per thread
#define SP 24
#define PCHUNK 288
#define TI 128

__device__ float4 d_triA[NB * NF];     // (Ax, Ay, Az, -0.5|A-B|^2)
__device__ float4 d_triB[NB * NF];     // (Bx, By, Bz, -0.5|B-C|^2)
__device__ float4 d_triC[NB * NF];     // (Cx, Cy, Cz, -0.5|C-A|^2)
__device__ float4 d_triN[NB * NF];     // (nx, ny, nz, d0)
__device__ float  d_wnp[SW][NB * NV];
__device__ float  d_pmin[SP][NB * NV];

__device__ __forceinline__ float rcp_fast(float x) {
    float r; asm("rcp.approx.f32 %0, %1;" : "=f"(r) : "f"(x)); return r;
}
__device__ __forceinline__ float sqrt_fast(float x) {
    float r; asm("sqrt.approx.f32 %0, %1;" : "=f"(r) : "f"(x)); return r;
}

// atan2 with quadrant handling folded into a sign flip (ALU) + constant add.
// Cases (f1 = |y|>|x|, f2 = x<0):  (0,0): a   (1,0): pi/2 - a
//                                  (1,1): pi/2 + a   (0,1): pi - a
// i.e. r = C + (f1^f2 ? -a : a), C = f1 ? pi/2 : (f2 ? pi : 0)
__device__ __forceinline__ float fast_atan2f(float y, float x) {
    float ax = fabsf(x), ay = fabsf(y);
    bool f1 = ay > ax;
    bool f2 = x < 0.0f;
    float mx = fmaxf(ax, ay), mn = fminf(ax, ay);
    float t = mn * rcp_fast(fmaxf(mx, 1e-37f));   // mx==0 -> t = 0
    unsigned sgn = (f1 != f2) ? 0x80000000u : 0u;
    t = __int_as_float(__float_as_int(t) ^ sgn);  // odd poly -> fold sign
    float s = t * t;
    float u;
    u = 0.00282363896258175373077393f;
    u = fmaf(u, s, -0.0159569028764963150024414f);
    u = fmaf(u, s,  0.0425049886107444763183594f);
    u = fmaf(u, s, -0.0748900920152664184570312f);
    u = fmaf(u, s,  0.106347933411598205566406f);
    u = fmaf(u, s, -0.142027363181114196777344f);
    u = fmaf(u, s,  0.199926957488059997558594f);
    u = fmaf(u, s, -0.333331018686294555664062f);
    float a = fmaf(u * s, t, t);
    float C = f1 ? 1.57079632679489662f
                 : (f2 ? 3.14159265358979323f : 0.0f);
    return copysignf(C + a, y);
}

// one point-triangle solid-angle contribution.
// npx/npy/npz are the NEGATED point coords (hoisted by caller).
__device__ __forceinline__ float wn_contrib(
    float npx, float npy, float npz,
    const float4& A, const float4& B, const float4& C, const float4& N)
{
    float ax = A.x + npx, ay = A.y + npy, az = A.z + npz;
    float bx = B.x + npx, by = B.y + npy, bz = B.z + npz;
    float cx = C.x + npx, cy = C.y + npy, cz = C.z + npz;

    float na2 = fmaf(ax, ax, fmaf(ay, ay, az * az));
    float nb2 = fmaf(bx, bx, fmaf(by, by, bz * bz));
    float nc2 = fmaf(cx, cx, fmaf(cy, cy, cz * cz));
    float na = sqrt_fast(na2);
    float nb = sqrt_fast(nb2);
    float nc = sqrt_fast(nc2);

    // Lagrange identity dots: a.b = 0.5*(na2+nb2) - 0.5|A-B|^2
    float ab = fmaf(0.5f, na2 + nb2, A.w);
    float bc = fmaf(0.5f, nb2 + nc2, B.w);
    float ca = fmaf(0.5f, nc2 + na2, C.w);

    // det[a;b;c] = d0 - p.n  =  fma chain on negated point
    float det = fmaf(npz, N.z, fmaf(npy, N.y, fmaf(npx, N.x, N.w)));

    // den = nc*(na*nb + ab) + (na*bc + nb*ca)
    float t1  = fmaf(na, nb, ab);
    float v   = fmaf(na, bc, nb * ca);
    float den = fmaf(nc, t1, v);

    float r = fast_atan2f(det, den);

    // p exactly a vertex -> reference atan2(0,0)=0; norms are exact diffs
    // so exactly zero iff coincident. (ALU-pipe select.)
    float m = fminf(fminf(na2, nb2), nc2);
    return (m == 0.0f) ? 0.0f : r;
}

__global__ void gather_tris(const float* __restrict__ verts,
                            const int* __restrict__ faces) {
    int idx = blockIdx.x * blockDim.x + threadIdx.x;
    if (idx >= NB * NF) return;
    int b = idx / NF, t = idx - b * NF;
    int i0 = faces[3 * t + 0];
    int i1 = faces[3 * t + 1];
    int i2 = faces[3 * t + 2];
    const float* vb = verts + (size_t)b * NV * 3;
    float Axv = vb[3*i0], Ayv = vb[3*i0+1], Azv = vb[3*i0+2];
    float Bxv = vb[3*i1], Byv = vb[3*i1+1], Bzv = vb[3*i1+2];
    float Cxv = vb[3*i2], Cyv = vb[3*i2+1], Czv = vb[3*i2+2];

    float ex = Axv-Bxv, ey = Ayv-Byv, ez = Azv-Bzv;
    float hAB = -0.5f * (fmaf(ex,ex,fmaf(ey,ey,ez*ez)));
    ex = Bxv-Cxv; ey = Byv-Cyv; ez = Bzv-Czv;
    float hBC = -0.5f * (fmaf(ex,ex,fmaf(ey,ey,ez*ez)));
    ex = Cxv-Axv; ey = Cyv-Ayv; ez = Czv-Azv;
    float hCA = -0.5f * (fmaf(ex,ex,fmaf(ey,ey,ez*ez)));

    d_triA[idx] = make_float4(Axv, Ayv, Azv, hAB);
    d_triB[idx] = make_float4(Bxv, Byv, Bzv, hBC);
    d_triC[idx] = make_float4(Cxv, Cyv, Czv, hCA);

    float bcx = fmaf(Byv, Czv, -(Bzv * Cyv));
    float bcy = fmaf(Bzv, Cxv, -(Bxv * Czv));
    float bcz = fmaf(Bxv, Cyv, -(Byv * Cxv));
    float abx = fmaf(Ayv, Bzv, -(Azv * Byv));
    float aby = fmaf(Azv, Bxv, -(Axv * Bzv));
    float abz = fmaf(Axv, Byv, -(Ayv * Bxv));
    float cax = fmaf(Cyv, Azv, -(Czv * Ayv));
    float cay = fmaf(Czv, Axv, -(Cxv * Azv));
    float caz = fmaf(Cxv, Ayv, -(Cyv * Axv));

    float nx = abx + bcx + cax;
    float ny = aby + bcy + cay;
    float nz = abz + bcz + caz;
    float d0 = fmaf(Azv, bcz, fmaf(Ayv, bcy, Axv * bcx));   // A.(BxC)
    d_triN[idx] = make_float4(nx, ny, nz, d0);
}

__global__ void __launch_bounds__(64) winding_kernel(const float* __restrict__ verts) {
    __shared__ float4 sA[WTILE], sB[WTILE], sC[WTILE], sN[WTILE];
    const int b = blockIdx.z;
    const int s = blockIdx.y;
    const int p0 = blockIdx.x * 64 + threadIdx.x;   // < PHALF
    const int p1r = p0 + PHALF;
    const int p1 = min(p1r, NV - 1);

    const float* vp0 = verts + ((size_t)b * NV + p0) * 3;
    const float npx0 = -vp0[0], npy0 = -vp0[1], npz0 = -vp0[2];
    const float* vp1 = verts + ((size_t)b * NV + p1) * 3;
    const float npx1 = -vp1[0], npy1 = -vp1[1], npz1 = -vp1[2];

    const int t0 = s * WCHUNK;
    const int t1 = t0 + WCHUNK;
    float acc0 = 0.f, acc1 = 0.f;

    for (int base = t0; base < t1; base += WTILE) {
        int cnt = min(WTILE, t1 - base);
        __syncthreads();
        for (int k = threadIdx.x; k < cnt; k += 64) {
            sA[k] = d_triA[b * NF + base + k];
            sB[k] = d_triB[b * NF + base + k];
            sC[k] = d_triC[b * NF + base + k];
            sN[k] = d_triN[b * NF + base + k];
        }
        __syncthreads();
        #pragma unroll 2
        for (int k = 0; k < cnt; k++) {
            float4 A = sA[k], B = sB[k], C = sC[k], N = sN[k];
            acc0 += wn_contrib(npx0, npy0, npz0, A, B, C, N);
            acc1 += wn_contrib(npx1, npy1, npz1, A, B, C, N);
        }
    }
    d_wnp[s][b * NV + p0] = acc0;
    if (p1r < NV) d_wnp[s][b * NV + p1r] = acc1;
}

__global__ void pairwise_kernel(const float* __restrict__ verts,
                                const int* __restrict__ gm) {
    __shared__ float sx0[TI], sy0[TI], sz0[TI], sq0[TI];
    __shared__ float sx1[TI], sy1[TI], sz1[TI], sq1[TI];

    const int s  = blockIdx.y;
    const int j0 = (blockIdx.x * blockDim.x + threadIdx.x) * 2;
    const bool jv = j0 < NV;

    float xa0=0,ya0=0,za0=0,qa0=0, xa1=0,ya1=0,za1=0,qa1=0;
    float xb0=0,yb0=0,zb0=0,qb0=0, xb1=0,yb1=0,zb1=0,qb1=0;
    if (jv) {
        const float* v = verts + (size_t)j0 * 3;
        xa0 = v[0]; ya0 = v[1]; za0 = v[2];
        xa1 = v[3]; ya1 = v[4]; za1 = v[5];
        qa0 = (xa0*xa0 + ya0*ya0) + za0*za0;
        qa1 = (xa1*xa1 + ya1*ya1) + za1*za1;
        const float* w = verts + ((size_t)NV + j0) * 3;
        xb0 = w[0]; yb0 = w[1]; zb0 = w[2];
        xb1 = w[3]; yb1 = w[4]; zb1 = w[5];
        qb0 = (xb0*xb0 + yb0*yb0) + zb0*zb0;
        qb1 = (xb1*xb1 + yb1*yb1) + zb1*zb1;
    }

    const float INF = __int_as_float(0x7f800000);
    float m00 = INF, m01 = INF, m10 = INF, m11 = INF;

    const int i0 = s * PCHUNK;
    const int i1 = min(NV, i0 + PCHUNK);

    for (int base = i0; base < i1; base += TI) {
        int cnt = min(TI, i1 - base);
        __syncthreads();
        for (int k = threadIdx.x; k < cnt; k += blockDim.x) {
            int i = base + k;
            const float* v = verts + (size_t)i * 3;
            float x = v[0], y = v[1], z = v[2];
            sx0[k] = x; sy0[k] = y; sz0[k] = z;
            sq0[k] = (x*x + y*y) + z*z;
            const float* w = verts + ((size_t)NV + i) * 3;
            x = w[0]; y = w[1]; z = w[2];
            sx1[k] = x; sy1[k] = y; sz1[k] = z;
            sq1[k] = (x*x + y*y) + z*z;
        }
        __syncthreads();
        if (jv) {
            const int* mp = gm + (size_t)base * NV + j0;
            for (int k = 0; k < cnt; k++) {
                int2 mm = *(const int2*)mp;
                mp += NV;
                float xi = sx0[k], yi = sy0[k], zi = sz0[k], qi = sq0[k];
                float dot0 = fmaf(zi, za0, fmaf(yi, ya0, xi * xa0));
                float d2_0 = fmaf(-2.f, dot0, qi + qa0);
                float dot1 = fmaf(zi, za1, fmaf(yi, ya1, xi * xa1));
                float d2_1 = fmaf(-2.f, dot1, qi + qa1);
                if (mm.x) m00 = fminf(m00, d2_0);
                if (mm.y) m01 = fminf(m01, d2_1);
                xi = sx1[k]; yi = sy1[k]; zi = sz1[k]; qi = sq1[k];
                float e0 = fmaf(zi, zb0, fmaf(yi, yb0, xi * xb0));
                float f0 = fmaf(-2.f, e0, qi + qb0);
                float e1 = fmaf(zi, zb1, fmaf(yi, yb1, xi * xb1));
                float f1 = fmaf(-2.f, e1, qi + qb1);
                if (mm.x) m10 = fminf(m10, f0);
                if (mm.y) m11 = fminf(m11, f1);
            }
        }
    }
    if (jv) {
        d_pmin[s][j0]          = m00;
        d_pmin[s][j0 + 1]      = m01;
        d_pmin[s][NV + j0]     = m10;
        d_pmin[s][NV + j0 + 1] = m11;
    }
}

__global__ void finalize_kernel(float* __restrict__ out) {
    int idx = blockIdx.x * blockDim.x + threadIdx.x;
    if (idx >= NB * NV) return;
    const float INF = __int_as_float(0x7f800000);
    float mn = INF;
    #pragma unroll
    for (int s = 0; s < SP; s++) mn = fminf(mn, d_pmin[s][idx]);
    float v = sqrtf(fmaxf(mn, 1e-12f));

    float acc = 0.f;
    #pragma unroll
    for (int s = 0; s < SW; s++) acc += d_wnp[s][idx];
    float wn = (2.0f * acc) / 12.566370614359172f;

    out[idx]               = v;
    out[NB * NV + idx]     = (v < 0.02f) ? 1.0f : 0.0f;
    out[2 * NB * NV + idx] = (wn <= 0.99f) ? 1.0f : 0.0f;
}

extern "C" void kernel_launch(void* const* d_in, const int* in_sizes, int n_in,
                              void* d_out, int out_size) {
    const float* verts = (const float*)d_in[0];
    const int*   faces = (const int*)d_in[1];
    const int*   gm    = (const int*)d_in[2];
    float* out = (float*)d_out;

    gather_tris<<<(NB * NF + 255) / 256, 256>>>(verts, faces);

    dim3 gw(54, SW, NB);                 // 54 x 16 x 2 = 1728 blocks, 64 thr
    winding_kernel<<<gw, 64>>>(verts);

    dim3 gp((NV + 511) / 512, SP);       // 336 blocks
    pairwise_kernel<<<gp, 256>>>(verts, gm);

    finalize_kernel<<<(NB * NV + 255) / 256, 256>>>(out);
}